// round 10
// baseline (speedup 1.0000x reference)
#include <cuda_runtime.h>
#include <cuda_bf16.h>

// Device-global scratch (no allocations allowed).
__device__ float    g_M1[104 * 100];   // level-1 partials (10-layer composites)
__device__ float    g_c1[104 * 10];
__device__ float    g_M3[100];         // final composed matrix [out][in] row-major
__device__ float    g_c3[10];          // final composed bias
__device__ unsigned g_ctr1;            // level-1 CTA arrivals (0..13)
__device__ unsigned g_flag;            // fold complete
__device__ unsigned g_done;            // CTA-done counter (reset logic)

#define TPB 256
#define NSTAGE 5
#define STAGE_PAIRS 240                      // 8 warps x 30 pairs
#define STAGE_FLOATS (STAGE_PAIRS * 20)      // 19200 B
#define STAGE0_F 128                         // stages start 512B in (128B-aligned)
#define SMEM_BYTES ((STAGE0_F + NSTAGE * STAGE_FLOATS) * 4)   // 96512 -> 2 CTAs/SM

// ---------------------------------------------------------------------------
// PTX helpers.
// ---------------------------------------------------------------------------
__device__ __forceinline__ unsigned smem_u32(const void* p) {
    unsigned r;
    asm("{ .reg .u64 t; cvta.to.shared.u64 t, %1; cvt.u32.u64 %0, t; }"
        : "=r"(r) : "l"(p));
    return r;
}
__device__ __forceinline__ void mbar_init(unsigned addr, unsigned count) {
    asm volatile("mbarrier.init.shared.b64 [%0], %1;" :: "r"(addr), "r"(count) : "memory");
}
__device__ __forceinline__ void mbar_expect_tx(unsigned addr, unsigned bytes) {
    asm volatile("mbarrier.arrive.expect_tx.shared.b64 _, [%0], %1;"
                 :: "r"(addr), "r"(bytes) : "memory");
}
__device__ __forceinline__ void bulk_load(unsigned dst_smem, const void* src_gmem,
                                          unsigned bytes, unsigned mbar) {
    asm volatile("cp.async.bulk.shared::cta.global.mbarrier::complete_tx::bytes "
                 "[%0], [%1], %2, [%3];"
                 :: "r"(dst_smem), "l"(src_gmem), "r"(bytes), "r"(mbar) : "memory");
}
__device__ __forceinline__ void mbar_wait(unsigned addr, unsigned parity) {
    unsigned done;
    asm volatile("{\n\t.reg .pred p;\n\t"
                 "mbarrier.try_wait.parity.acquire.cta.shared::cta.b64 p, [%1], %2;\n\t"
                 "selp.b32 %0, 1, 0, p;\n\t}"
                 : "=r"(done) : "r"(addr), "r"(parity) : "memory");
    while (!done) {
        asm volatile("{\n\t.reg .pred p;\n\t"
                     "mbarrier.try_wait.parity.acquire.cta.shared::cta.b64 p, [%1], %2, 0x989680;\n\t"
                     "selp.b32 %0, 1, 0, p;\n\t}"
                     : "=r"(done) : "r"(addr), "r"(parity) : "memory");
    }
}
__device__ __forceinline__ unsigned long long pack2(float lo, float hi) {
    unsigned long long r;
    asm("mov.b64 %0, {%1, %2};" : "=l"(r) : "f"(lo), "f"(hi));
    return r;
}
__device__ __forceinline__ void unpack2(unsigned long long v, float& lo, float& hi) {
    asm("mov.b64 {%0, %1}, %2;" : "=f"(lo), "=f"(hi) : "l"(v));
}
__device__ __forceinline__ void ffma2(unsigned long long& d, unsigned long long a,
                                      unsigned long long b) {
    asm("fma.rn.f32x2 %0, %1, %2, %0;" : "+l"(d) : "l"(a), "l"(b));
}

// ---------------------------------------------------------------------------
// Warp-level fold of a chain of n affine maps in smem (validated R9).
// Lane j<10 ends with column j of the composite; lane 10 with the bias.
// ---------------------------------------------------------------------------
__device__ __forceinline__ void warp_fold_chain(const float* __restrict__ Wsm,
                                                const float* __restrict__ bsm,
                                                int n, int lane, float m[10]) {
    #pragma unroll
    for (int k = 0; k < 10; ++k)
        m[k] = (lane < 10) ? Wsm[k * 10 + lane] : bsm[k];

    #pragma unroll 1
    for (int s = 1; s < n; ++s) {
        const float2* Wr = (const float2*)(Wsm + s * 100);
        float acc[10];
        #pragma unroll
        for (int i = 0; i < 10; ++i) {
            const float2 w0 = Wr[i * 5 + 0];
            const float2 w1 = Wr[i * 5 + 1];
            const float2 w2 = Wr[i * 5 + 2];
            const float2 w3 = Wr[i * 5 + 3];
            const float2 w4 = Wr[i * 5 + 4];
            float a;
            a = w0.x * m[0];
            a = fmaf(w0.y, m[1], a);
            a = fmaf(w1.x, m[2], a);
            a = fmaf(w1.y, m[3], a);
            a = fmaf(w2.x, m[4], a);
            a = fmaf(w2.y, m[5], a);
            a = fmaf(w3.x, m[6], a);
            a = fmaf(w3.y, m[7], a);
            a = fmaf(w4.x, m[8], a);
            a = fmaf(w4.y, m[9], a);
            acc[i] = a;
        }
        if (lane == 10) {
            #pragma unroll
            for (int i = 0; i < 10; ++i) acc[i] += bsm[s * 10 + i];
        }
        #pragma unroll
        for (int i = 0; i < 10; ++i) m[i] = acc[i];
    }
}
__device__ __forceinline__ void warp_copy4(float* dst, const float* src,
                                           int nfloats, int lane) {
    const float4* s4 = (const float4*)src;
    float4* d4 = (float4*)dst;
    for (int i = lane; i < nfloats / 4; i += 32) d4[i] = s4[i];
}
__device__ __forceinline__ void warp_copy1(float* dst, const float* src,
                                           int nfloats, int lane) {
    for (int i = lane; i < nfloats; i += 32) dst[i] = src[i];
}

__device__ __forceinline__ void issue_tile(float* SH, unsigned bar_s, int s,
                                           long long tile, long long pairs,
                                           const float* x) {
    const long long pbase = tile * STAGE_PAIRS;
    const long long rem = pairs - pbase;
    const unsigned np = (unsigned)(rem < STAGE_PAIRS ? rem : STAGE_PAIRS);
    mbar_expect_tx(bar_s, np * 80u);
    bulk_load(smem_u32(&SH[STAGE0_F + s * STAGE_FLOATS]), x + pbase * 20, np * 80u, bar_s);
}

// ---------------------------------------------------------------------------
// ONE fused kernel (grid=296, 2 CTAs/SM, wave-1):
//  - CTAs >=14: issue ONLY stages 0-1 at t=0 (10.8MB burst, not 27MB) so the
//    fold's dependent loads aren't latency-inflated by DRAM congestion.
//  - CTAs 0..12: warp-fold 8 chunks each -> g_M1; CTA 13: level 2+3 -> g_M3,
//    sets g_flag. Fold CTAs issue their full prologue after folding.
//  - All: wait flag, issue remaining stages, run static-tiled TMA-pipelined
//    apply with even/odd f32x2 FMA (no runtime packs).
// ---------------------------------------------------------------------------
__global__ void __launch_bounds__(TPB, 2) fused_kernel(const float* __restrict__ Ws,
                                                       const float* __restrict__ bs,
                                                       const float* __restrict__ x,
                                                       float* __restrict__ out,
                                                       long long pairs,
                                                       long long rows) {
    extern __shared__ float SH[];
    const int tid  = threadIdx.x;
    const int cta  = blockIdx.x;
    const int lane = tid & 31;
    const int warp = tid >> 5;

    unsigned bar[NSTAGE];
    #pragma unroll
    for (int s = 0; s < NSTAGE; ++s) bar[s] = smem_u32(&SH[s * 2]);
    if (tid == 0) {
        #pragma unroll
        for (int s = 0; s < NSTAGE; ++s) mbar_init(bar[s], 1);
    }
    __syncthreads();

    const long long tiles   = (pairs + STAGE_PAIRS - 1) / STAGE_PAIRS;
    const long long gstride = gridDim.x;

    // ---- t=0: reduced prefill for non-fold CTAs (stages 0,1 only) ----
    if (cta >= 14) {
        if (tid == 0) {
            #pragma unroll
            for (int s = 0; s < 2; ++s) {
                const long long t = cta + (long long)s * gstride;
                if (t < tiles) issue_tile(SH, bar[s], s, t, pairs, x);
            }
        }
    } else if (cta < 13) {
        // ---- Level 1: warp folds chunk cta*8+warp (layers [10c,10c+10)) ----
        const int chunk = cta * 8 + warp;
        float* slot = SH + STAGE0_F + warp * 1104;   // 1000 W + 100 b
        if (chunk < 100) {
            warp_copy4(slot,        Ws + (size_t)chunk * 1000, 1000, lane);
            warp_copy4(slot + 1000, bs + (size_t)chunk * 100,  100,  lane);
            __syncwarp();
            float m[10];
            warp_fold_chain(slot, slot + 1000, 10, lane, m);
            if (lane < 10) {
                #pragma unroll
                for (int k = 0; k < 10; ++k) g_M1[chunk * 100 + k * 10 + lane] = m[k];
            } else if (lane == 10) {
                #pragma unroll
                for (int k = 0; k < 10; ++k) g_c1[chunk * 10 + k] = m[k];
            }
        }
        __threadfence();
        __syncthreads();
        if (tid == 0) atomicAdd(&g_ctr1, 1u);
    } else { // cta == 13: levels 2 & 3
        if (tid == 0) {
            while (*(volatile unsigned*)&g_ctr1 < 13u) __nanosleep(32);
        }
        __syncthreads();
        __threadfence();   // acquire

        const int len   = (warp < 4) ? 13 : 12;      // 4*13 + 4*12 = 100
        const int start = (warp < 4) ? warp * 13 : 52 + (warp - 4) * 12;
        float* slot = SH + STAGE0_F + warp * 1440;   // 1300 W + 130 b
        float* W3   = SH + STAGE0_F + 8 * 1440;      // 800
        float* b3   = W3 + 800;                      // 80

        warp_copy4(slot,        g_M1 + start * 100, len * 100, lane);
        warp_copy1(slot + 1300, g_c1 + start * 10,  len * 10,  lane);
        __syncwarp();
        float m[10];
        warp_fold_chain(slot, slot + 1300, len, lane, m);
        if (lane < 10) {
            #pragma unroll
            for (int k = 0; k < 10; ++k) W3[warp * 100 + k * 10 + lane] = m[k];
        } else if (lane == 10) {
            #pragma unroll
            for (int k = 0; k < 10; ++k) b3[warp * 10 + k] = m[k];
        }
        __syncthreads();
        if (warp == 0) {
            float mm[10];
            warp_fold_chain(W3, b3, 8, lane, mm);
            if (lane < 10) {
                #pragma unroll
                for (int k = 0; k < 10; ++k) g_M3[k * 10 + lane] = mm[k];
            } else if (lane == 10) {
                #pragma unroll
                for (int k = 0; k < 10; ++k) g_c3[k] = mm[k];
            }
        }
        __threadfence();
        __syncthreads();
        if (tid == 0) *(volatile unsigned*)&g_flag = 1u;
    }

    // ---- Wait for composed affine ----
    if (tid == 0) {
        while (*(volatile unsigned*)&g_flag == 0u) __nanosleep(32);
    }
    __syncthreads();
    __threadfence();   // acquire

    // ---- Issue the remaining stages (fold CTAs: all; others: stages 2..4) ----
    if (tid == 0) {
        const int s0 = (cta >= 14) ? 2 : 0;
        for (int s = s0; s < NSTAGE; ++s) {
            const long long t = cta + (long long)s * gstride;
            if (t < tiles) issue_tile(SH, bar[s], s, t, pairs, x);
        }
    }

    // Per-lane constants: phase = lane%5 -> 4 consecutive output floats.
    const int phase = lane % 5;
    const int lp    = lane / 5;              // 5-lane group (0..5; 6 inactive)
    const bool active = (lane < 30);
    const int offA = (phase >= 3) ? 10 : 0;  // source row for outputs w=0,1
    const int offB = (phase >= 2) ? 10 : 0;  // source row for outputs w=2,3
    const int j0 = (4 * phase + 0) % 10;
    const int j1 = (4 * phase + 1) % 10;
    const int j2 = (4 * phase + 2) % 10;
    const int j3 = (4 * phase + 3) % 10;

    // Loop-invariant even/odd M packs: Mwj[kk] = (M[j][2kk], M[j][2kk+1]).
    unsigned long long Mw0[5], Mw1[5], Mw2[5], Mw3[5];
    #pragma unroll
    for (int kk = 0; kk < 5; ++kk) {
        Mw0[kk] = pack2(__ldg(&g_M3[j0 * 10 + 2 * kk]), __ldg(&g_M3[j0 * 10 + 2 * kk + 1]));
        Mw1[kk] = pack2(__ldg(&g_M3[j1 * 10 + 2 * kk]), __ldg(&g_M3[j1 * 10 + 2 * kk + 1]));
        Mw2[kk] = pack2(__ldg(&g_M3[j2 * 10 + 2 * kk]), __ldg(&g_M3[j2 * 10 + 2 * kk + 1]));
        Mw3[kk] = pack2(__ldg(&g_M3[j3 * 10 + 2 * kk]), __ldg(&g_M3[j3 * 10 + 2 * kk + 1]));
    }
    const unsigned long long C0 = pack2(__ldg(&g_c3[j0]), 0.f);
    const unsigned long long C1 = pack2(__ldg(&g_c3[j1]), 0.f);
    const unsigned long long C2 = pack2(__ldg(&g_c3[j2]), 0.f);
    const unsigned long long C3 = pack2(__ldg(&g_c3[j3]), 0.f);

    float4* out4 = (float4*)out;

    // ---- Main pipelined apply ----
    long long i = 0;
    #pragma unroll 1
    for (long long t = cta; t < tiles; t += gstride, ++i) {
        const int s = (int)(i % NSTAGE);
        const unsigned parity = (unsigned)((i / NSTAGE) & 1);
        mbar_wait(bar[s], parity);

        const float* st = &SH[STAGE0_F + s * STAGE_FLOATS];
        const long long tb = t * STAGE_PAIRS;

        #pragma unroll
        for (int it = 0; it < 5; ++it) {
            const int p = warp * 30 + it * 6 + lp;
            const long long gp = tb + p;
            if (active && gp < pairs) {
                const unsigned long long* rA =
                    (const unsigned long long*)(st + p * 20 + offA);
                const unsigned long long* rB =
                    (const unsigned long long*)(st + p * 20 + offB);
                unsigned long long s0 = C0, s1 = C1, s2 = C2, s3 = C3;
                #pragma unroll
                for (int kk = 0; kk < 5; ++kk) {
                    const unsigned long long a = rA[kk];   // (h[2kk], h[2kk+1]) row A
                    const unsigned long long b = rB[kk];   // row B
                    ffma2(s0, Mw0[kk], a);
                    ffma2(s1, Mw1[kk], a);
                    ffma2(s2, Mw2[kk], b);
                    ffma2(s3, Mw3[kk], b);
                }
                float ev, od, o0, o1, o2, o3;
                unpack2(s0, ev, od); o0 = ev + od;
                unpack2(s1, ev, od); o1 = ev + od;
                unpack2(s2, ev, od); o2 = ev + od;
                unpack2(s3, ev, od); o3 = ev + od;
                out4[gp * 5 + phase] = make_float4(o0, o1, o2, o3);
            }
        }

        __syncthreads();   // all warps done reading stage s
        const long long tn = t + (long long)NSTAGE * gstride;
        if (tn < tiles && tid == 0) issue_tile(SH, bar[s], s, tn, pairs, x);
    }

    // Odd-row tail (rows is even here; kept for safety).
    if ((rows & 1LL) && cta == 0 && tid == 0) {
        const long long r = rows - 1;
        const float* xr = x + r * 10;
        float h[10];
        #pragma unroll
        for (int k = 0; k < 10; ++k) h[k] = xr[k];
        float* orow = out + r * 10;
        #pragma unroll
        for (int j = 0; j < 10; ++j) {
            float a = __ldg(&g_c3[j]);
            #pragma unroll
            for (int k = 0; k < 10; ++k) a += h[k] * __ldg(&g_M3[j * 10 + k]);
            orow[j] = a;
        }
    }

    // ---- Reset (replay-safe; last-finishing CTA) ----
    __syncthreads();
    __threadfence();
    if (tid == 0) {
        const unsigned old = atomicAdd(&g_done, 1u);
        if (old == gridDim.x - 1) {
            g_done = 0;
            g_ctr1 = 0;
            g_flag = 0;
        }
    }
}

extern "C" void kernel_launch(void* const* d_in, const int* in_sizes, int n_in,
                              void* d_out, int out_size) {
    // Identify inputs by element count: x=BATCH*10, Ws=1000*100, bs=1000*10.
    const float* x  = nullptr;
    const float* Ws = nullptr;
    const float* bs = nullptr;
    long long x_elems = 0;
    for (int i = 0; i < n_in; ++i) {
        if (in_sizes[i] == 1000 * 100) {
            Ws = (const float*)d_in[i];
        } else if (in_sizes[i] == 1000 * 10) {
            bs = (const float*)d_in[i];
        } else {
            x = (const float*)d_in[i];
            x_elems = in_sizes[i];
        }
    }
    const long long rows  = x_elems / 10;
    const long long pairs = rows >> 1;

    static int smem_set = 0;
    if (!smem_set) {
        cudaFuncSetAttribute(fused_kernel,
                             cudaFuncAttributeMaxDynamicSharedMemorySize, SMEM_BYTES);
        smem_set = 1;
    }
    // Single graph node: 296 CTAs = 2/SM (96.5KB smem) -> wave-1, spin-safe.
    fused_kernel<<<296, TPB, SMEM_BYTES>>>(Ws, bs, x, (float*)d_out, pairs, rows);
}

// round 11
// speedup vs baseline: 1.0755x; 1.0755x over previous
#include <cuda_runtime.h>
#include <cuda_bf16.h>

// Device-global scratch (no allocations allowed).
__device__ float    g_P[25 * 112];     // 25 CTA partials: 100 matrix + 10 bias + pad
__device__ float    g_M3[100];         // final composed matrix [out][in] row-major
__device__ float    g_c3[10];          // final composed bias
__device__ unsigned g_ctr1;            // partial arrivals from CTAs 1..24
__device__ unsigned g_flag;            // fold complete
__device__ unsigned g_done;            // CTA-done counter (reset logic)

#define TPB 256
#define NFOLD 25                             // fold CTAs (200 warps, 5 layers each)
#define NSTAGE 5
#define STAGE_PAIRS 240                      // 8 warps x 30 pairs
#define STAGE_FLOATS (STAGE_PAIRS * 20)      // 19200 B
#define STAGE0_F 128                         // stages start 512B in
#define SMEM_BYTES ((STAGE0_F + NSTAGE * STAGE_FLOATS) * 4)   // 96512 -> 2 CTAs/SM

// ---------------------------------------------------------------------------
// PTX helpers.
// ---------------------------------------------------------------------------
__device__ __forceinline__ unsigned smem_u32(const void* p) {
    unsigned r;
    asm("{ .reg .u64 t; cvta.to.shared.u64 t, %1; cvt.u32.u64 %0, t; }"
        : "=r"(r) : "l"(p));
    return r;
}
__device__ __forceinline__ void mbar_init(unsigned addr, unsigned count) {
    asm volatile("mbarrier.init.shared.b64 [%0], %1;" :: "r"(addr), "r"(count) : "memory");
}
__device__ __forceinline__ void mbar_expect_tx(unsigned addr, unsigned bytes) {
    asm volatile("mbarrier.arrive.expect_tx.shared.b64 _, [%0], %1;"
                 :: "r"(addr), "r"(bytes) : "memory");
}
__device__ __forceinline__ void bulk_load(unsigned dst_smem, const void* src_gmem,
                                          unsigned bytes, unsigned mbar) {
    asm volatile("cp.async.bulk.shared::cta.global.mbarrier::complete_tx::bytes "
                 "[%0], [%1], %2, [%3];"
                 :: "r"(dst_smem), "l"(src_gmem), "r"(bytes), "r"(mbar) : "memory");
}
__device__ __forceinline__ void mbar_wait(unsigned addr, unsigned parity) {
    unsigned done;
    asm volatile("{\n\t.reg .pred p;\n\t"
                 "mbarrier.try_wait.parity.acquire.cta.shared::cta.b64 p, [%1], %2;\n\t"
                 "selp.b32 %0, 1, 0, p;\n\t}"
                 : "=r"(done) : "r"(addr), "r"(parity) : "memory");
    while (!done) {
        asm volatile("{\n\t.reg .pred p;\n\t"
                     "mbarrier.try_wait.parity.acquire.cta.shared::cta.b64 p, [%1], %2, 0x989680;\n\t"
                     "selp.b32 %0, 1, 0, p;\n\t}"
                     : "=r"(done) : "r"(addr), "r"(parity) : "memory");
    }
}
__device__ __forceinline__ unsigned long long pack2(float lo, float hi) {
    unsigned long long r;
    asm("mov.b64 %0, {%1, %2};" : "=l"(r) : "f"(lo), "f"(hi));
    return r;
}
__device__ __forceinline__ void unpack2(unsigned long long v, float& lo, float& hi) {
    asm("mov.b64 {%0, %1}, %2;" : "=f"(lo), "=f"(hi) : "l"(v));
}
__device__ __forceinline__ void ffma2(unsigned long long& d, unsigned long long a,
                                      unsigned long long b) {
    asm("fma.rn.f32x2 %0, %1, %2, %0;" : "+l"(d) : "l"(a), "l"(b));
}

// ---------------------------------------------------------------------------
// Fold primitives. Partial layout: 112 floats = [0,100) matrix row-major,
// [100,110) bias, 2 pad. Lane j<10 carries column j; lane 10 carries the bias.
// ---------------------------------------------------------------------------
__device__ __forceinline__ void apply_step(const float* __restrict__ B,
                                           const float* __restrict__ bbias,
                                           int lane, float m[10]) {
    const float2* Br = (const float2*)B;
    float acc[10];
    #pragma unroll
    for (int i = 0; i < 10; ++i) {
        const float2 w0 = Br[i * 5 + 0];
        const float2 w1 = Br[i * 5 + 1];
        const float2 w2 = Br[i * 5 + 2];
        const float2 w3 = Br[i * 5 + 3];
        const float2 w4 = Br[i * 5 + 4];
        float a;
        a = w0.x * m[0];
        a = fmaf(w0.y, m[1], a);
        a = fmaf(w1.x, m[2], a);
        a = fmaf(w1.y, m[3], a);
        a = fmaf(w2.x, m[4], a);
        a = fmaf(w2.y, m[5], a);
        a = fmaf(w3.x, m[6], a);
        a = fmaf(w3.y, m[7], a);
        a = fmaf(w4.x, m[8], a);
        a = fmaf(w4.y, m[9], a);
        acc[i] = a;
    }
    if (lane == 10) {
        #pragma unroll
        for (int i = 0; i < 10; ++i) acc[i] += bbias[i];
    }
    #pragma unroll
    for (int i = 0; i < 10; ++i) m[i] = acc[i];
}

// Chain of n maps (W stride 100, b stride 10) -> composite in m.
__device__ __forceinline__ void warp_fold_chain(const float* __restrict__ Wsm,
                                                const float* __restrict__ bsm,
                                                int n, int lane, float m[10]) {
    #pragma unroll
    for (int k = 0; k < 10; ++k)
        m[k] = (lane < 10) ? Wsm[k * 10 + lane] : bsm[k];
    #pragma unroll 1
    for (int s = 1; s < n; ++s)
        apply_step(Wsm + s * 100, bsm + s * 10, lane, m);
}

// Pairwise: m := B ∘ A  (A applied first), A/B in partial layout.
__device__ __forceinline__ void warp_fold2(const float* __restrict__ A,
                                           const float* __restrict__ B,
                                           int lane, float m[10]) {
    #pragma unroll
    for (int k = 0; k < 10; ++k)
        m[k] = (lane < 10) ? A[k * 10 + lane] : A[100 + k];
    apply_step(B, B + 100, lane, m);
}

__device__ __forceinline__ void store_partial(float* __restrict__ D,
                                              const float m[10], int lane) {
    if (lane < 10) {
        #pragma unroll
        for (int k = 0; k < 10; ++k) D[k * 10 + lane] = m[k];
    } else if (lane == 10) {
        #pragma unroll
        for (int k = 0; k < 10; ++k) D[100 + k] = m[k];
    }
}

__device__ __forceinline__ void warp_copy4(float* dst, const float* src,
                                           int nfloats, int lane) {
    const float4* s4 = (const float4*)src;
    float4* d4 = (float4*)dst;
    #pragma unroll 4
    for (int i = lane; i < nfloats / 4; i += 32) d4[i] = s4[i];
}
__device__ __forceinline__ void warp_copy1(float* dst, const float* src,
                                           int nfloats, int lane) {
    for (int i = lane; i < nfloats; i += 32) dst[i] = src[i];
}

__device__ __forceinline__ void issue_tile(float* SH, unsigned bar_s, int s,
                                           long long tile, long long pairs,
                                           const float* x) {
    const long long pbase = tile * STAGE_PAIRS;
    const long long rem = pairs - pbase;
    const unsigned np = (unsigned)(rem < STAGE_PAIRS ? rem : STAGE_PAIRS);
    mbar_expect_tx(bar_s, np * 80u);
    bulk_load(smem_u32(&SH[STAGE0_F + s * STAGE_FLOATS]), x + pbase * 20, np * 80u, bar_s);
}

// ---------------------------------------------------------------------------
// ONE fused kernel (grid=296 = 2 CTAs/SM, wave-1):
//  - CTAs >= 25: full TMA prologue at t=0.
//  - CTAs 0..24: fold. Level1: each warp folds 5 layers (4 serial steps).
//    Intra-CTA pairwise 8->4->2->1 (3 steps) -> g_P[cta]. CTA0 waits for 24
//    arrivals, pairwise-reduces 25 partials (6 rounds) -> g_M3/g_c3, sets flag.
//    Fold CTAs issue their prologue right after their fold work.
//  - All: wait flag, then static-tiled TMA-pipelined apply with even/odd
//    f32x2 FMA (no runtime packs).
// ---------------------------------------------------------------------------
__global__ void __launch_bounds__(TPB, 2) fused_kernel(const float* __restrict__ Ws,
                                                       const float* __restrict__ bs,
                                                       const float* __restrict__ x,
                                                       float* __restrict__ out,
                                                       long long pairs,
                                                       long long rows) {
    extern __shared__ float SH[];
    const int tid  = threadIdx.x;
    const int cta  = blockIdx.x;
    const int lane = tid & 31;
    const int warp = tid >> 5;

    unsigned bar[NSTAGE];
    #pragma unroll
    for (int s = 0; s < NSTAGE; ++s) bar[s] = smem_u32(&SH[s * 2]);
    if (tid == 0) {
        #pragma unroll
        for (int s = 0; s < NSTAGE; ++s) mbar_init(bar[s], 1);
    }
    __syncthreads();

    const long long tiles   = (pairs + STAGE_PAIRS - 1) / STAGE_PAIRS;
    const long long gstride = gridDim.x;

    if (cta >= NFOLD) {
        // ---- Non-fold CTAs: full prologue immediately ----
        if (tid == 0) {
            #pragma unroll
            for (int s = 0; s < NSTAGE; ++s) {
                const long long t = cta + (long long)s * gstride;
                if (t < tiles) issue_tile(SH, bar[s], s, t, pairs, x);
            }
        }
    } else {
        // ---- Level 1: warp folds chunk = cta*8+warp (5 layers) ----
        const int chunk = cta * 8 + warp;                  // 0..199
        float* slot = SH + STAGE0_F + warp * 560;          // 500 W + 50 b + pad
        float* PA   = SH + STAGE0_F + 8 * 560;             // 8 x 112
        float* PB   = PA + 8 * 112;                        // 4 x 112

        warp_copy4(slot,       Ws + (size_t)chunk * 500, 500, lane);
        warp_copy1(slot + 500, bs + (size_t)chunk * 50,  50,  lane);
        __syncwarp();
        float m[10];
        warp_fold_chain(slot, slot + 500, 5, lane, m);
        store_partial(PA + warp * 112, m, lane);
        __syncthreads();

        // ---- Intra-CTA pairwise: 8 -> 4 -> 2 -> 1 ----
        if (warp < 4) {
            warp_fold2(PA + (2 * warp) * 112, PA + (2 * warp + 1) * 112, lane, m);
            store_partial(PB + warp * 112, m, lane);
        }
        __syncthreads();
        if (warp < 2) {
            warp_fold2(PB + (2 * warp) * 112, PB + (2 * warp + 1) * 112, lane, m);
            store_partial(PA + warp * 112, m, lane);
        }
        __syncthreads();
        if (warp == 0) {
            warp_fold2(PA, PA + 112, lane, m);
            store_partial(g_P + cta * 112, m, lane);   // direct global write
        }
        __threadfence();
        __syncthreads();

        if (cta != 0) {
            if (tid == 0) atomicAdd(&g_ctr1, 1u);
        } else {
            // ---- CTA 0: final pairwise reduce of 25 partials ----
            if (tid == 0) {
                while (*(volatile unsigned*)&g_ctr1 < 24u) __nanosleep(32);
            }
            __syncthreads();
            __threadfence();   // acquire

            float* SA = SH + STAGE0_F;          // 25 x 112 = 2800
            float* SB = SA + 2800;              // up to 13 x 112
            for (int i = tid; i < 25 * 112; i += TPB) SA[i] = g_P[i];
            __syncthreads();

            float* src = SA;
            float* dst = SB;
            int cnt = 25;
            while (cnt > 1) {
                const int half = cnt >> 1;
                for (int w = warp; w < half; w += 8) {
                    float mm[10];
                    warp_fold2(src + (2 * w) * 112, src + (2 * w + 1) * 112, lane, mm);
                    store_partial(dst + w * 112, mm, lane);
                }
                __syncthreads();
                if (cnt & 1) {
                    for (int i = tid; i < 112; i += TPB)
                        dst[half * 112 + i] = src[(cnt - 1) * 112 + i];
                    __syncthreads();
                }
                cnt = half + (cnt & 1);
                float* tp = src; src = dst; dst = tp;
            }
            for (int i = tid; i < 100; i += TPB) g_M3[i] = src[i];
            if (tid < 10) g_c3[tid] = src[100 + tid];
            __threadfence();
            __syncthreads();
            if (tid == 0) *(volatile unsigned*)&g_flag = 1u;
        }

        // ---- Fold CTAs: prologue after fold (stage smem now free) ----
        if (tid == 0) {
            #pragma unroll
            for (int s = 0; s < NSTAGE; ++s) {
                const long long t = cta + (long long)s * gstride;
                if (t < tiles) issue_tile(SH, bar[s], s, t, pairs, x);
            }
        }
    }

    // ================= WAIT FOR THE COMPOSED AFFINE =================
    if (tid == 0) {
        while (*(volatile unsigned*)&g_flag == 0u) __nanosleep(32);
    }
    __syncthreads();
    __threadfence();   // acquire

    // Per-lane constants: phase = lane%5 -> 4 consecutive output floats.
    const int phase = lane % 5;
    const int lp    = lane / 5;              // 5-lane group (0..5; 6 inactive)
    const bool active = (lane < 30);
    const int offA = (phase >= 3) ? 10 : 0;  // source row for outputs w=0,1
    const int offB = (phase >= 2) ? 10 : 0;  // source row for outputs w=2,3
    const int j0 = (4 * phase + 0) % 10;
    const int j1 = (4 * phase + 1) % 10;
    const int j2 = (4 * phase + 2) % 10;
    const int j3 = (4 * phase + 3) % 10;

    // Loop-invariant even/odd M packs: Mwj[kk] = (M[j][2kk], M[j][2kk+1]).
    unsigned long long Mw0[5], Mw1[5], Mw2[5], Mw3[5];
    #pragma unroll
    for (int kk = 0; kk < 5; ++kk) {
        Mw0[kk] = pack2(__ldg(&g_M3[j0 * 10 + 2 * kk]), __ldg(&g_M3[j0 * 10 + 2 * kk + 1]));
        Mw1[kk] = pack2(__ldg(&g_M3[j1 * 10 + 2 * kk]), __ldg(&g_M3[j1 * 10 + 2 * kk + 1]));
        Mw2[kk] = pack2(__ldg(&g_M3[j2 * 10 + 2 * kk]), __ldg(&g_M3[j2 * 10 + 2 * kk + 1]));
        Mw3[kk] = pack2(__ldg(&g_M3[j3 * 10 + 2 * kk]), __ldg(&g_M3[j3 * 10 + 2 * kk + 1]));
    }
    const unsigned long long C0 = pack2(__ldg(&g_c3[j0]), 0.f);
    const unsigned long long C1 = pack2(__ldg(&g_c3[j1]), 0.f);
    const unsigned long long C2 = pack2(__ldg(&g_c3[j2]), 0.f);
    const unsigned long long C3 = pack2(__ldg(&g_c3[j3]), 0.f);

    float4* out4 = (float4*)out;

    // ================= APPLY (static tiles, TMA pipeline) =================
    long long i = 0;
    #pragma unroll 1
    for (long long t = cta; t < tiles; t += gstride, ++i) {
        const int s = (int)(i % NSTAGE);
        const unsigned parity = (unsigned)((i / NSTAGE) & 1);
        mbar_wait(bar[s], parity);

        const float* st = &SH[STAGE0_F + s * STAGE_FLOATS];
        const long long tb = t * STAGE_PAIRS;

        #pragma unroll
        for (int it = 0; it < 5; ++it) {
            const int p = warp * 30 + it * 6 + lp;
            const long long gp = tb + p;
            if (active && gp < pairs) {
                const unsigned long long* rA =
                    (const unsigned long long*)(st + p * 20 + offA);
                const unsigned long long* rB =
                    (const unsigned long long*)(st + p * 20 + offB);
                unsigned long long s0 = C0, s1 = C1, s2 = C2, s3 = C3;
                #pragma unroll
                for (int kk = 0; kk < 5; ++kk) {
                    const unsigned long long a = rA[kk];   // (h[2kk],h[2kk+1]) row A
                    const unsigned long long b = rB[kk];   // row B
                    ffma2(s0, Mw0[kk], a);
                    ffma2(s1, Mw1[kk], a);
                    ffma2(s2, Mw2[kk], b);
                    ffma2(s3, Mw3[kk], b);
                }
                float ev, od, o0, o1, o2, o3;
                unpack2(s0, ev, od); o0 = ev + od;
                unpack2(s1, ev, od); o1 = ev + od;
                unpack2(s2, ev, od); o2 = ev + od;
                unpack2(s3, ev, od); o3 = ev + od;
                out4[gp * 5 + phase] = make_float4(o0, o1, o2, o3);
            }
        }

        __syncthreads();   // all warps done reading stage s
        const long long tn = t + (long long)NSTAGE * gstride;
        if (tn < tiles && tid == 0) issue_tile(SH, bar[s], s, tn, pairs, x);
    }

    // Odd-row tail (rows is even here; kept for safety).
    if ((rows & 1LL) && cta == 0 && tid == 0) {
        const long long r = rows - 1;
        const float* xr = x + r * 10;
        float h[10];
        #pragma unroll
        for (int k = 0; k < 10; ++k) h[k] = xr[k];
        float* orow = out + r * 10;
        #pragma unroll
        for (int j = 0; j < 10; ++j) {
            float a = __ldg(&g_c3[j]);
            #pragma unroll
            for (int k = 0; k < 10; ++k) a += h[k] * __ldg(&g_M3[j * 10 + k]);
            orow[j] = a;
        }
    }

    // ================= RESET (replay-safe; last-finishing CTA) ===============
    __syncthreads();
    __threadfence();
    if (tid == 0) {
        const unsigned old = atomicAdd(&g_done, 1u);
        if (old == gridDim.x - 1) {
            g_done = 0;
            g_ctr1 = 0;
            g_flag = 0;
        }
    }
}

extern "C" void kernel_launch(void* const* d_in, const int* in_sizes, int n_in,
                              void* d_out, int out_size) {
    // Identify inputs by element count: x=BATCH*10, Ws=1000*100, bs=1000*10.
    const float* x  = nullptr;
    const float* Ws = nullptr;
    const float* bs = nullptr;
    long long x_elems = 0;
    for (int i = 0; i < n_in; ++i) {
        if (in_sizes[i] == 1000 * 100) {
            Ws = (const float*)d_in[i];
        } else if (in_sizes[i] == 1000 * 10) {
            bs = (const float*)d_in[i];
        } else {
            x = (const float*)d_in[i];
            x_elems = in_sizes[i];
        }
    }
    const long long rows  = x_elems / 10;
    const long long pairs = rows >> 1;

    static int smem_set = 0;
    if (!smem_set) {
        cudaFuncSetAttribute(fused_kernel,
                             cudaFuncAttributeMaxDynamicSharedMemorySize, SMEM_BYTES);
        smem_set = 1;
    }
    // Single graph node: 296 CTAs = 2/SM (96.5KB smem) -> wave-1, spin-safe.
    fused_kernel<<<296, TPB, SMEM_BYTES>>>(Ws, bs, x, (float*)d_out, pairs, rows);
}

// round 12
// speedup vs baseline: 1.0876x; 1.0112x over previous
#include <cuda_runtime.h>
#include <cuda_bf16.h>

// Device-global scratch (no allocations allowed).
__device__ float    g_P[25 * 112];     // 25 CTA partials: 100 matrix + 10 bias + pad
__device__ float    g_M3[100];         // final composed matrix [out][in] row-major
__device__ float    g_c3[10];          // final composed bias
__device__ unsigned g_ctr1;            // partial arrivals from CTAs 1..24
__device__ unsigned g_flag;            // fold complete
__device__ unsigned g_done;            // CTA-done counter (reset logic)

#define TPB 256
#define NFOLD 25                             // fold CTAs (200 warps, 5 layers each)
#define NSTAGE 5
#define STAGE_PAIRS 240                      // 8 warps x 30 pairs
#define STAGE_FLOATS (STAGE_PAIRS * 20)      // 19200 B
#define STAGE0_F 128                         // stages start 512B in
#define SMEM_BYTES ((STAGE0_F + NSTAGE * STAGE_FLOATS) * 4)   // 96512 -> 2 CTAs/SM

// ---------------------------------------------------------------------------
// PTX helpers.
// ---------------------------------------------------------------------------
__device__ __forceinline__ unsigned smem_u32(const void* p) {
    unsigned r;
    asm("{ .reg .u64 t; cvta.to.shared.u64 t, %1; cvt.u32.u64 %0, t; }"
        : "=r"(r) : "l"(p));
    return r;
}
__device__ __forceinline__ void mbar_init(unsigned addr, unsigned count) {
    asm volatile("mbarrier.init.shared.b64 [%0], %1;" :: "r"(addr), "r"(count) : "memory");
}
__device__ __forceinline__ void mbar_expect_tx(unsigned addr, unsigned bytes) {
    asm volatile("mbarrier.arrive.expect_tx.shared.b64 _, [%0], %1;"
                 :: "r"(addr), "r"(bytes) : "memory");
}
__device__ __forceinline__ void bulk_load(unsigned dst_smem, const void* src_gmem,
                                          unsigned bytes, unsigned mbar) {
    asm volatile("cp.async.bulk.shared::cta.global.mbarrier::complete_tx::bytes "
                 "[%0], [%1], %2, [%3];"
                 :: "r"(dst_smem), "l"(src_gmem), "r"(bytes), "r"(mbar) : "memory");
}
__device__ __forceinline__ void mbar_wait(unsigned addr, unsigned parity) {
    unsigned done;
    asm volatile("{\n\t.reg .pred p;\n\t"
                 "mbarrier.try_wait.parity.acquire.cta.shared::cta.b64 p, [%1], %2;\n\t"
                 "selp.b32 %0, 1, 0, p;\n\t}"
                 : "=r"(done) : "r"(addr), "r"(parity) : "memory");
    while (!done) {
        asm volatile("{\n\t.reg .pred p;\n\t"
                     "mbarrier.try_wait.parity.acquire.cta.shared::cta.b64 p, [%1], %2, 0x989680;\n\t"
                     "selp.b32 %0, 1, 0, p;\n\t}"
                     : "=r"(done) : "r"(addr), "r"(parity) : "memory");
    }
}

// ---------------------------------------------------------------------------
// Fold primitives. Partial layout: 112 floats = [0,100) matrix row-major,
// [100,110) bias, 2 pad. Lane j<10 carries column j; lane 10 carries the bias.
// ---------------------------------------------------------------------------
__device__ __forceinline__ void apply_step(const float* __restrict__ B,
                                           const float* __restrict__ bbias,
                                           int lane, float m[10]) {
    const float2* Br = (const float2*)B;
    float acc[10];
    #pragma unroll
    for (int i = 0; i < 10; ++i) {
        const float2 w0 = Br[i * 5 + 0];
        const float2 w1 = Br[i * 5 + 1];
        const float2 w2 = Br[i * 5 + 2];
        const float2 w3 = Br[i * 5 + 3];
        const float2 w4 = Br[i * 5 + 4];
        float a;
        a = w0.x * m[0];
        a = fmaf(w0.y, m[1], a);
        a = fmaf(w1.x, m[2], a);
        a = fmaf(w1.y, m[3], a);
        a = fmaf(w2.x, m[4], a);
        a = fmaf(w2.y, m[5], a);
        a = fmaf(w3.x, m[6], a);
        a = fmaf(w3.y, m[7], a);
        a = fmaf(w4.x, m[8], a);
        a = fmaf(w4.y, m[9], a);
        acc[i] = a;
    }
    if (lane == 10) {
        #pragma unroll
        for (int i = 0; i < 10; ++i) acc[i] += bbias[i];
    }
    #pragma unroll
    for (int i = 0; i < 10; ++i) m[i] = acc[i];
}

// Chain of n maps (W stride 100, b stride 10) -> composite in m.
__device__ __forceinline__ void warp_fold_chain(const float* __restrict__ Wsm,
                                                const float* __restrict__ bsm,
                                                int n, int lane, float m[10]) {
    #pragma unroll
    for (int k = 0; k < 10; ++k)
        m[k] = (lane < 10) ? Wsm[k * 10 + lane] : bsm[k];
    #pragma unroll 1
    for (int s = 1; s < n; ++s)
        apply_step(Wsm + s * 100, bsm + s * 10, lane, m);
}

// Pairwise: m := B ∘ A  (A applied first), A/B in partial layout.
__device__ __forceinline__ void warp_fold2(const float* __restrict__ A,
                                           const float* __restrict__ B,
                                           int lane, float m[10]) {
    #pragma unroll
    for (int k = 0; k < 10; ++k)
        m[k] = (lane < 10) ? A[k * 10 + lane] : A[100 + k];
    apply_step(B, B + 100, lane, m);
}

__device__ __forceinline__ void store_partial(float* __restrict__ D,
                                              const float m[10], int lane) {
    if (lane < 10) {
        #pragma unroll
        for (int k = 0; k < 10; ++k) D[k * 10 + lane] = m[k];
    } else if (lane == 10) {
        #pragma unroll
        for (int k = 0; k < 10; ++k) D[100 + k] = m[k];
    }
}

__device__ __forceinline__ void warp_copy4(float* dst, const float* src,
                                           int nfloats, int lane) {
    const float4* s4 = (const float4*)src;
    float4* d4 = (float4*)dst;
    #pragma unroll 4
    for (int i = lane; i < nfloats / 4; i += 32) d4[i] = s4[i];
}
__device__ __forceinline__ void warp_copy1(float* dst, const float* src,
                                           int nfloats, int lane) {
    for (int i = lane; i < nfloats; i += 32) dst[i] = src[i];
}

__device__ __forceinline__ void issue_tile(float* SH, unsigned bar_s, int s,
                                           long long tile, long long pairs,
                                           const float* x) {
    const long long pbase = tile * STAGE_PAIRS;
    const long long rem = pairs - pbase;
    const unsigned np = (unsigned)(rem < STAGE_PAIRS ? rem : STAGE_PAIRS);
    mbar_expect_tx(bar_s, np * 80u);
    bulk_load(smem_u32(&SH[STAGE0_F + s * STAGE_FLOATS]), x + pbase * 20, np * 80u, bar_s);
}

// ---------------------------------------------------------------------------
// ONE fused kernel (grid=296 = 2 CTAs/SM, wave-1):
//  - CTAs >= 25: full TMA prologue at t=0.
//  - CTAs 0..24: R11 fold (level1: 5 layers/warp = 4 steps; intra-CTA pairwise
//    8->4->2->1; CTA0 pairwise-reduces 25 partials) -> g_M3/g_c3, sets flag.
//  - All: wait flag, then static-tiled TMA-pipelined apply with plain fmaf
//    (R6-proven inner loop: float2 LDS reads, 40 scalar FFMA).
// ---------------------------------------------------------------------------
__global__ void __launch_bounds__(TPB, 2) fused_kernel(const float* __restrict__ Ws,
                                                       const float* __restrict__ bs,
                                                       const float* __restrict__ x,
                                                       float* __restrict__ out,
                                                       long long pairs,
                                                       long long rows) {
    extern __shared__ float SH[];
    const int tid  = threadIdx.x;
    const int cta  = blockIdx.x;
    const int lane = tid & 31;
    const int warp = tid >> 5;

    unsigned bar[NSTAGE];
    #pragma unroll
    for (int s = 0; s < NSTAGE; ++s) bar[s] = smem_u32(&SH[s * 2]);
    if (tid == 0) {
        #pragma unroll
        for (int s = 0; s < NSTAGE; ++s) mbar_init(bar[s], 1);
    }
    __syncthreads();

    const long long tiles   = (pairs + STAGE_PAIRS - 1) / STAGE_PAIRS;
    const long long gstride = gridDim.x;

    if (cta >= NFOLD) {
        // ---- Non-fold CTAs: full prologue immediately ----
        if (tid == 0) {
            #pragma unroll
            for (int s = 0; s < NSTAGE; ++s) {
                const long long t = cta + (long long)s * gstride;
                if (t < tiles) issue_tile(SH, bar[s], s, t, pairs, x);
            }
        }
    } else {
        // ---- Level 1: warp folds chunk = cta*8+warp (5 layers) ----
        const int chunk = cta * 8 + warp;                  // 0..199
        float* slot = SH + STAGE0_F + warp * 560;          // 500 W + 50 b + pad
        float* PA   = SH + STAGE0_F + 8 * 560;             // 8 x 112
        float* PB   = PA + 8 * 112;                        // 4 x 112

        warp_copy4(slot,       Ws + (size_t)chunk * 500, 500, lane);
        warp_copy1(slot + 500, bs + (size_t)chunk * 50,  50,  lane);
        __syncwarp();
        float m[10];
        warp_fold_chain(slot, slot + 500, 5, lane, m);
        store_partial(PA + warp * 112, m, lane);
        __syncthreads();

        // ---- Intra-CTA pairwise: 8 -> 4 -> 2 -> 1 ----
        if (warp < 4) {
            warp_fold2(PA + (2 * warp) * 112, PA + (2 * warp + 1) * 112, lane, m);
            store_partial(PB + warp * 112, m, lane);
        }
        __syncthreads();
        if (warp < 2) {
            warp_fold2(PB + (2 * warp) * 112, PB + (2 * warp + 1) * 112, lane, m);
            store_partial(PA + warp * 112, m, lane);
        }
        __syncthreads();
        if (warp == 0) {
            warp_fold2(PA, PA + 112, lane, m);
            store_partial(g_P + cta * 112, m, lane);   // direct global write
        }
        __threadfence();
        __syncthreads();

        if (cta != 0) {
            if (tid == 0) atomicAdd(&g_ctr1, 1u);
        } else {
            // ---- CTA 0: final pairwise reduce of 25 partials ----
            if (tid == 0) {
                while (*(volatile unsigned*)&g_ctr1 < 24u) __nanosleep(32);
            }
            __syncthreads();
            __threadfence();   // acquire

            float* SA = SH + STAGE0_F;          // 25 x 112 = 2800
            float* SB = SA + 2800;              // up to 13 x 112
            for (int i = tid; i < 25 * 112; i += TPB) SA[i] = g_P[i];
            __syncthreads();

            float* src = SA;
            float* dst = SB;
            int cnt = 25;
            while (cnt > 1) {
                const int half = cnt >> 1;
                for (int w = warp; w < half; w += 8) {
                    float mm[10];
                    warp_fold2(src + (2 * w) * 112, src + (2 * w + 1) * 112, lane, mm);
                    store_partial(dst + w * 112, mm, lane);
                }
                __syncthreads();
                if (cnt & 1) {
                    for (int i = tid; i < 112; i += TPB)
                        dst[half * 112 + i] = src[(cnt - 1) * 112 + i];
                    __syncthreads();
                }
                cnt = half + (cnt & 1);
                float* tp = src; src = dst; dst = tp;
            }
            for (int i = tid; i < 100; i += TPB) g_M3[i] = src[i];
            if (tid < 10) g_c3[tid] = src[100 + tid];
            __threadfence();
            __syncthreads();
            if (tid == 0) *(volatile unsigned*)&g_flag = 1u;
        }

        // ---- Fold CTAs: prologue after fold (stage smem now free) ----
        if (tid == 0) {
            #pragma unroll
            for (int s = 0; s < NSTAGE; ++s) {
                const long long t = cta + (long long)s * gstride;
                if (t < tiles) issue_tile(SH, bar[s], s, t, pairs, x);
            }
        }
    }

    // ================= WAIT FOR THE COMPOSED AFFINE =================
    if (tid == 0) {
        while (*(volatile unsigned*)&g_flag == 0u) __nanosleep(32);
    }
    __syncthreads();
    __threadfence();   // acquire

    // Per-lane constants: phase = lane%5 -> 4 consecutive output floats.
    const int phase = lane % 5;
    const int lp    = lane / 5;              // 5-lane group (0..5; 6 inactive)
    const bool active = (lane < 30);
    const int offA = (phase >= 3) ? 10 : 0;  // source row for outputs w=0,1
    const int offB = (phase >= 2) ? 10 : 0;  // source row for outputs w=2,3

    // Per-lane M rows + biases into registers (R6-proven plain-fmaf form).
    float mw[40], cw[4];
    #pragma unroll
    for (int w = 0; w < 4; ++w) {
        const int jw = (4 * phase + w) % 10;
        cw[w] = __ldg(&g_c3[jw]);
        #pragma unroll
        for (int k = 0; k < 10; ++k) mw[w * 10 + k] = __ldg(&g_M3[jw * 10 + k]);
    }

    float4* out4 = (float4*)out;

    // ================= APPLY (static tiles, TMA pipeline, plain fmaf) ========
    long long i = 0;
    #pragma unroll 1
    for (long long t = cta; t < tiles; t += gstride, ++i) {
        const int s = (int)(i % NSTAGE);
        const unsigned parity = (unsigned)((i / NSTAGE) & 1);
        mbar_wait(bar[s], parity);

        const float* st = &SH[STAGE0_F + s * STAGE_FLOATS];
        const long long tb = t * STAGE_PAIRS;

        #pragma unroll
        for (int it = 0; it < 5; ++it) {
            const int p = warp * 30 + it * 6 + lp;
            const long long gp = tb + p;
            if (active && gp < pairs) {
                const float2* rA = (const float2*)(st + p * 20 + offA);
                const float2* rB = (const float2*)(st + p * 20 + offB);
                float o0 = cw[0], o1 = cw[1], o2 = cw[2], o3 = cw[3];
                #pragma unroll
                for (int kk = 0; kk < 5; ++kk) {
                    const float2 a = rA[kk];
                    const float2 b = rB[kk];
                    o0 = fmaf(mw[2 * kk],          a.x, o0);
                    o0 = fmaf(mw[2 * kk + 1],      a.y, o0);
                    o1 = fmaf(mw[10 + 2 * kk],     a.x, o1);
                    o1 = fmaf(mw[10 + 2 * kk + 1], a.y, o1);
                    o2 = fmaf(mw[20 + 2 * kk],     b.x, o2);
                    o2 = fmaf(mw[20 + 2 * kk + 1], b.y, o2);
                    o3 = fmaf(mw[30 + 2 * kk],     b.x, o3);
                    o3 = fmaf(mw[30 + 2 * kk + 1], b.y, o3);
                }
                out4[gp * 5 + phase] = make_float4(o0, o1, o2, o3);
            }
        }

        __syncthreads();   // all warps done reading stage s
        const long long tn = t + (long long)NSTAGE * gstride;
        if (tn < tiles && tid == 0) issue_tile(SH, bar[s], s, tn, pairs, x);
    }

    // Odd-row tail (rows is even here; kept for safety).
    if ((rows & 1LL) && cta == 0 && tid == 0) {
        const long long r = rows - 1;
        const float* xr = x + r * 10;
        float h[10];
        #pragma unroll
        for (int k = 0; k < 10; ++k) h[k] = xr[k];
        float* orow = out + r * 10;
        #pragma unroll
        for (int j = 0; j < 10; ++j) {
            float a = __ldg(&g_c3[j]);
            #pragma unroll
            for (int k = 0; k < 10; ++k) a += h[k] * __ldg(&g_M3[j * 10 + k]);
            orow[j] = a;
        }
    }

    // ================= RESET (replay-safe; last-finishing CTA) ===============
    __syncthreads();
    __threadfence();
    if (tid == 0) {
        const unsigned old = atomicAdd(&g_done, 1u);
        if (old == gridDim.x - 1) {
            g_done = 0;
            g_ctr1 = 0;
            g_flag = 0;
        }
    }
}

extern "C" void kernel_launch(void* const* d_in, const int* in_sizes, int n_in,
                              void* d_out, int out_size) {
    // Identify inputs by element count: x=BATCH*10, Ws=1000*100, bs=1000*10.
    const float* x  = nullptr;
    const float* Ws = nullptr;
    const float* bs = nullptr;
    long long x_elems = 0;
    for (int i = 0; i < n_in; ++i) {
        if (in_sizes[i] == 1000 * 100) {
            Ws = (const float*)d_in[i];
        } else if (in_sizes[i] == 1000 * 10) {
            bs = (const float*)d_in[i];
        } else {
            x = (const float*)d_in[i];
            x_elems = in_sizes[i];
        }
    }
    const long long rows  = x_elems / 10;
    const long long pairs = rows >> 1;

    static int smem_set = 0;
    if (!smem_set) {
        cudaFuncSetAttribute(fused_kernel,
                             cudaFuncAttributeMaxDynamicSharedMemorySize, SMEM_BYTES);
        smem_set = 1;
    }
    // Single graph node: 296 CTAs = 2/SM (96.5KB smem) -> wave-1, spin-safe.
    fused_kernel<<<296, TPB, SMEM_BYTES>>>(Ws, bs, x, (float*)d_out, pairs, rows);
}

// round 13
// speedup vs baseline: 1.0907x; 1.0028x over previous
#include <cuda_runtime.h>
#include <cuda_bf16.h>

// Device-global scratch (no allocations allowed).
__device__ float    g_P[25 * 112];     // 25 CTA partials: 100 matrix + 10 bias + pad
__device__ float    g_M3[100];         // final composed matrix [out][in] row-major
__device__ float    g_c3[10];          // final composed bias
__device__ unsigned g_wload;           // fold-warp weight-load arrivals (0..200)
__device__ unsigned g_ctr1;            // partial arrivals from CTAs 1..24
__device__ unsigned g_flag;            // fold complete
__device__ unsigned g_done;            // CTA-done counter (reset logic)

#define TPB 256
#define NFOLD 25                             // fold CTAs (200 warps, 5 layers each)
#define NSTAGE 5
#define STAGE_PAIRS 240                      // 8 warps x 30 pairs
#define STAGE_FLOATS (STAGE_PAIRS * 20)      // 19200 B
#define STAGE0_F 128                         // stages start 512B in
#define SMEM_BYTES ((STAGE0_F + NSTAGE * STAGE_FLOATS) * 4)   // 96512 -> 2 CTAs/SM

// ---------------------------------------------------------------------------
// PTX helpers.
// ---------------------------------------------------------------------------
__device__ __forceinline__ unsigned smem_u32(const void* p) {
    unsigned r;
    asm("{ .reg .u64 t; cvta.to.shared.u64 t, %1; cvt.u32.u64 %0, t; }"
        : "=r"(r) : "l"(p));
    return r;
}
__device__ __forceinline__ void mbar_init(unsigned addr, unsigned count) {
    asm volatile("mbarrier.init.shared.b64 [%0], %1;" :: "r"(addr), "r"(count) : "memory");
}
__device__ __forceinline__ void mbar_expect_tx(unsigned addr, unsigned bytes) {
    asm volatile("mbarrier.arrive.expect_tx.shared.b64 _, [%0], %1;"
                 :: "r"(addr), "r"(bytes) : "memory");
}
__device__ __forceinline__ void bulk_load(unsigned dst_smem, const void* src_gmem,
                                          unsigned bytes, unsigned mbar) {
    asm volatile("cp.async.bulk.shared::cta.global.mbarrier::complete_tx::bytes "
                 "[%0], [%1], %2, [%3];"
                 :: "r"(dst_smem), "l"(src_gmem), "r"(bytes), "r"(mbar) : "memory");
}
__device__ __forceinline__ void mbar_wait(unsigned addr, unsigned parity) {
    unsigned done;
    asm volatile("{\n\t.reg .pred p;\n\t"
                 "mbarrier.try_wait.parity.acquire.cta.shared::cta.b64 p, [%1], %2;\n\t"
                 "selp.b32 %0, 1, 0, p;\n\t}"
                 : "=r"(done) : "r"(addr), "r"(parity) : "memory");
    while (!done) {
        asm volatile("{\n\t.reg .pred p;\n\t"
                     "mbarrier.try_wait.parity.acquire.cta.shared::cta.b64 p, [%1], %2, 0x989680;\n\t"
                     "selp.b32 %0, 1, 0, p;\n\t}"
                     : "=r"(done) : "r"(addr), "r"(parity) : "memory");
    }
}

// ---------------------------------------------------------------------------
// Fold primitives. Partial layout: 112 floats = [0,100) matrix row-major,
// [100,110) bias, 2 pad. Lane j<10 carries column j; lane 10 carries the bias.
// ---------------------------------------------------------------------------
__device__ __forceinline__ void apply_step(const float* __restrict__ B,
                                           const float* __restrict__ bbias,
                                           int lane, float m[10]) {
    const float2* Br = (const float2*)B;
    float acc[10];
    #pragma unroll
    for (int i = 0; i < 10; ++i) {
        const float2 w0 = Br[i * 5 + 0];
        const float2 w1 = Br[i * 5 + 1];
        const float2 w2 = Br[i * 5 + 2];
        const float2 w3 = Br[i * 5 + 3];
        const float2 w4 = Br[i * 5 + 4];
        float a;
        a = w0.x * m[0];
        a = fmaf(w0.y, m[1], a);
        a = fmaf(w1.x, m[2], a);
        a = fmaf(w1.y, m[3], a);
        a = fmaf(w2.x, m[4], a);
        a = fmaf(w2.y, m[5], a);
        a = fmaf(w3.x, m[6], a);
        a = fmaf(w3.y, m[7], a);
        a = fmaf(w4.x, m[8], a);
        a = fmaf(w4.y, m[9], a);
        acc[i] = a;
    }
    if (lane == 10) {
        #pragma unroll
        for (int i = 0; i < 10; ++i) acc[i] += bbias[i];
    }
    #pragma unroll
    for (int i = 0; i < 10; ++i) m[i] = acc[i];
}

// Chain of n maps (W stride 100, b stride 10) -> composite in m.
__device__ __forceinline__ void warp_fold_chain(const float* __restrict__ Wsm,
                                                const float* __restrict__ bsm,
                                                int n, int lane, float m[10]) {
    #pragma unroll
    for (int k = 0; k < 10; ++k)
        m[k] = (lane < 10) ? Wsm[k * 10 + lane] : bsm[k];
    #pragma unroll 1
    for (int s = 1; s < n; ++s)
        apply_step(Wsm + s * 100, bsm + s * 10, lane, m);
}

// Pairwise: m := B ∘ A  (A applied first), A/B in partial layout.
__device__ __forceinline__ void warp_fold2(const float* __restrict__ A,
                                           const float* __restrict__ B,
                                           int lane, float m[10]) {
    #pragma unroll
    for (int k = 0; k < 10; ++k)
        m[k] = (lane < 10) ? A[k * 10 + lane] : A[100 + k];
    apply_step(B, B + 100, lane, m);
}

__device__ __forceinline__ void store_partial(float* __restrict__ D,
                                              const float m[10], int lane) {
    if (lane < 10) {
        #pragma unroll
        for (int k = 0; k < 10; ++k) D[k * 10 + lane] = m[k];
    } else if (lane == 10) {
        #pragma unroll
        for (int k = 0; k < 10; ++k) D[100 + k] = m[k];
    }
}

__device__ __forceinline__ void warp_copy4(float* dst, const float* src,
                                           int nfloats, int lane) {
    const float4* s4 = (const float4*)src;
    float4* d4 = (float4*)dst;
    #pragma unroll 4
    for (int i = lane; i < nfloats / 4; i += 32) d4[i] = s4[i];
}
__device__ __forceinline__ void warp_copy1(float* dst, const float* src,
                                           int nfloats, int lane) {
    for (int i = lane; i < nfloats; i += 32) dst[i] = src[i];
}

__device__ __forceinline__ void issue_tile(float* SH, unsigned bar_s, int s,
                                           long long tile, long long pairs,
                                           const float* x) {
    const long long pbase = tile * STAGE_PAIRS;
    const long long rem = pairs - pbase;
    const unsigned np = (unsigned)(rem < STAGE_PAIRS ? rem : STAGE_PAIRS);
    mbar_expect_tx(bar_s, np * 80u);
    bulk_load(smem_u32(&SH[STAGE0_F + s * STAGE_FLOATS]), x + pbase * 20, np * 80u, bar_s);
}

// ---------------------------------------------------------------------------
// ONE fused kernel (grid=296 = 2 CTAs/SM, wave-1):
//  - CTAs 0..24: fold. Each warp LDG-copies its 5 layers into smem, bumps
//    g_wload, then folds (4 steps) + intra-CTA pairwise 8->4->2->1 -> g_P.
//    CTA0 waits for all partials, pairwise-reduces 25 (6 rounds) -> g_M3/g_c3,
//    sets g_flag.
//  - CTAs >= 25: WAIT for g_wload==200 (fold weight loads done, DRAM clean),
//    THEN issue the full TMA prologue (runs concurrent with fold compute).
//  - All: wait g_flag, then static-tiled TMA-pipelined apply (plain fmaf).
// ---------------------------------------------------------------------------
__global__ void __launch_bounds__(TPB, 2) fused_kernel(const float* __restrict__ Ws,
                                                       const float* __restrict__ bs,
                                                       const float* __restrict__ x,
                                                       float* __restrict__ out,
                                                       long long pairs,
                                                       long long rows) {
    extern __shared__ float SH[];
    const int tid  = threadIdx.x;
    const int cta  = blockIdx.x;
    const int lane = tid & 31;
    const int warp = tid >> 5;

    unsigned bar[NSTAGE];
    #pragma unroll
    for (int s = 0; s < NSTAGE; ++s) bar[s] = smem_u32(&SH[s * 2]);
    if (tid == 0) {
        #pragma unroll
        for (int s = 0; s < NSTAGE; ++s) mbar_init(bar[s], 1);
    }
    __syncthreads();

    const long long tiles   = (pairs + STAGE_PAIRS - 1) / STAGE_PAIRS;
    const long long gstride = gridDim.x;

    if (cta >= NFOLD) {
        // ---- Non-fold CTAs: hold prologue until fold weight loads are done ----
        if (tid == 0) {
            while (*(volatile unsigned*)&g_wload < 200u) __nanosleep(32);
            #pragma unroll
            for (int s = 0; s < NSTAGE; ++s) {
                const long long t = cta + (long long)s * gstride;
                if (t < tiles) issue_tile(SH, bar[s], s, t, pairs, x);
            }
        }
    } else {
        // ---- Level 1: warp folds chunk = cta*8+warp (5 layers) ----
        const int chunk = cta * 8 + warp;                  // 0..199
        float* slot = SH + STAGE0_F + warp * 560;          // 500 W + 50 b + pad
        float* PA   = SH + STAGE0_F + 8 * 560;             // 8 x 112
        float* PB   = PA + 8 * 112;                        // 4 x 112

        warp_copy4(slot,       Ws + (size_t)chunk * 500, 500, lane);
        warp_copy1(slot + 500, bs + (size_t)chunk * 50,  50,  lane);
        __syncwarp();
        if (lane == 0) atomicAdd(&g_wload, 1u);            // weights staged
        float m[10];
        warp_fold_chain(slot, slot + 500, 5, lane, m);
        store_partial(PA + warp * 112, m, lane);
        __syncthreads();

        // ---- Intra-CTA pairwise: 8 -> 4 -> 2 -> 1 ----
        if (warp < 4) {
            warp_fold2(PA + (2 * warp) * 112, PA + (2 * warp + 1) * 112, lane, m);
            store_partial(PB + warp * 112, m, lane);
        }
        __syncthreads();
        if (warp < 2) {
            warp_fold2(PB + (2 * warp) * 112, PB + (2 * warp + 1) * 112, lane, m);
            store_partial(PA + warp * 112, m, lane);
        }
        __syncthreads();
        if (warp == 0) {
            warp_fold2(PA, PA + 112, lane, m);
            store_partial(g_P + cta * 112, m, lane);   // direct global write
        }
        __threadfence();
        __syncthreads();

        if (cta != 0) {
            if (tid == 0) atomicAdd(&g_ctr1, 1u);
        } else {
            // ---- CTA 0: final pairwise reduce of 25 partials ----
            if (tid == 0) {
                while (*(volatile unsigned*)&g_ctr1 < 24u) __nanosleep(32);
            }
            __syncthreads();
            __threadfence();   // acquire

            float* SA = SH + STAGE0_F;          // 25 x 112 = 2800
            float* SB = SA + 2800;              // up to 13 x 112
            for (int i = tid; i < 25 * 112; i += TPB) SA[i] = g_P[i];
            __syncthreads();

            float* src = SA;
            float* dst = SB;
            int cnt = 25;
            while (cnt > 1) {
                const int half = cnt >> 1;
                for (int w = warp; w < half; w += 8) {
                    float mm[10];
                    warp_fold2(src + (2 * w) * 112, src + (2 * w + 1) * 112, lane, mm);
                    store_partial(dst + w * 112, mm, lane);
                }
                __syncthreads();
                if (cnt & 1) {
                    for (int i = tid; i < 112; i += TPB)
                        dst[half * 112 + i] = src[(cnt - 1) * 112 + i];
                    __syncthreads();
                }
                cnt = half + (cnt & 1);
                float* tp = src; src = dst; dst = tp;
            }
            for (int i = tid; i < 100; i += TPB) g_M3[i] = src[i];
            if (tid < 10) g_c3[tid] = src[100 + tid];
            __threadfence();
            __syncthreads();
            if (tid == 0) *(volatile unsigned*)&g_flag = 1u;
        }

        // ---- Fold CTAs: prologue after their fold work (stage smem free) ----
        if (tid == 0) {
            #pragma unroll
            for (int s = 0; s < NSTAGE; ++s) {
                const long long t = cta + (long long)s * gstride;
                if (t < tiles) issue_tile(SH, bar[s], s, t, pairs, x);
            }
        }
    }

    // ================= WAIT FOR THE COMPOSED AFFINE =================
    if (tid == 0) {
        while (*(volatile unsigned*)&g_flag == 0u) __nanosleep(32);
    }
    __syncthreads();
    __threadfence();   // acquire

    // Per-lane constants: phase = lane%5 -> 4 consecutive output floats.
    const int phase = lane % 5;
    const int lp    = lane / 5;              // 5-lane group (0..5; 6 inactive)
    const bool active = (lane < 30);
    const int offA = (phase >= 3) ? 10 : 0;  // source row for outputs w=0,1
    const int offB = (phase >= 2) ? 10 : 0;  // source row for outputs w=2,3

    // Per-lane M rows + biases into registers (R6-proven plain-fmaf form).
    float mw[40], cw[4];
    #pragma unroll
    for (int w = 0; w < 4; ++w) {
        const int jw = (4 * phase + w) % 10;
        cw[w] = __ldg(&g_c3[jw]);
        #pragma unroll
        for (int k = 0; k < 10; ++k) mw[w * 10 + k] = __ldg(&g_M3[jw * 10 + k]);
    }

    float4* out4 = (float4*)out;

    // ================= APPLY (static tiles, TMA pipeline, plain fmaf) ========
    long long i = 0;
    #pragma unroll 1
    for (long long t = cta; t < tiles; t += gstride, ++i) {
        const int s = (int)(i % NSTAGE);
        const unsigned parity = (unsigned)((i / NSTAGE) & 1);
        mbar_wait(bar[s], parity);

        const float* st = &SH[STAGE0_F + s * STAGE_FLOATS];
        const long long tb = t * STAGE_PAIRS;

        #pragma unroll
        for (int it = 0; it < 5; ++it) {
            const int p = warp * 30 + it * 6 + lp;
            const long long gp = tb + p;
            if (active && gp < pairs) {
                const float2* rA = (const float2*)(st + p * 20 + offA);
                const float2* rB = (const float2*)(st + p * 20 + offB);
                float o0 = cw[0], o1 = cw[1], o2 = cw[2], o3 = cw[3];
                #pragma unroll
                for (int kk = 0; kk < 5; ++kk) {
                    const float2 a = rA[kk];
                    const float2 b = rB[kk];
                    o0 = fmaf(mw[2 * kk],          a.x, o0);
                    o0 = fmaf(mw[2 * kk + 1],      a.y, o0);
                    o1 = fmaf(mw[10 + 2 * kk],     a.x, o1);
                    o1 = fmaf(mw[10 + 2 * kk + 1], a.y, o1);
                    o2 = fmaf(mw[20 + 2 * kk],     b.x, o2);
                    o2 = fmaf(mw[20 + 2 * kk + 1], b.y, o2);
                    o3 = fmaf(mw[30 + 2 * kk],     b.x, o3);
                    o3 = fmaf(mw[30 + 2 * kk + 1], b.y, o3);
                }
                out4[gp * 5 + phase] = make_float4(o0, o1, o2, o3);
            }
        }

        __syncthreads();   // all warps done reading stage s
        const long long tn = t + (long long)NSTAGE * gstride;
        if (tn < tiles && tid == 0) issue_tile(SH, bar[s], s, tn, pairs, x);
    }

    // Odd-row tail (rows is even here; kept for safety).
    if ((rows & 1LL) && cta == 0 && tid == 0) {
        const long long r = rows - 1;
        const float* xr = x + r * 10;
        float h[10];
        #pragma unroll
        for (int k = 0; k < 10; ++k) h[k] = xr[k];
        float* orow = out + r * 10;
        #pragma unroll
        for (int j = 0; j < 10; ++j) {
            float a = __ldg(&g_c3[j]);
            #pragma unroll
            for (int k = 0; k < 10; ++k) a += h[k] * __ldg(&g_M3[j * 10 + k]);
            orow[j] = a;
        }
    }

    // ================= RESET (replay-safe; last-finishing CTA) ===============
    __syncthreads();
    __threadfence();
    if (tid == 0) {
        const unsigned old = atomicAdd(&g_done, 1u);
        if (old == gridDim.x - 1) {
            g_done  = 0;
            g_ctr1  = 0;
            g_wload = 0;
            g_flag  = 0;
        }
    }
}

extern "C" void kernel_launch(void* const* d_in, const int* in_sizes, int n_in,
                              void* d_out, int out_size) {
    // Identify inputs by element count: x=BATCH*10, Ws=1000*100, bs=1000*10.
    const float* x  = nullptr;
    const float* Ws = nullptr;
    const float* bs = nullptr;
    long long x_elems = 0;
    for (int i = 0; i < n_in; ++i) {
        if (in_sizes[i] == 1000 * 100) {
            Ws = (const float*)d_in[i];
        } else if (in_sizes[i] == 1000 * 10) {
            bs = (const float*)d_in[i];
        } else {
            x = (const float*)d_in[i];
            x_elems = in_sizes[i];
        }
    }
    const long long rows  = x_elems / 10;
    const long long pairs = rows >> 1;

    static int smem_set = 0;
    if (!smem_set) {
        cudaFuncSetAttribute(fused_kernel,
                             cudaFuncAttributeMaxDynamicSharedMemorySize, SMEM_BYTES);
        smem_set = 1;
    }
    // Single graph node: 296 CTAs = 2/SM (96.5KB smem) -> wave-1, spin-safe.
    fused_kernel<<<296, TPB, SMEM_BYTES>>>(Ws, bs, x, (float*)d_out, pairs, rows);
}